// round 17
// baseline (speedup 1.0000x reference)
#include <cuda_runtime.h>

// ---------------- problem constants ----------------
#define B_SZ   32
#define NROWS  48
#define NCOLS  24
#define CIN    32
#define HID    256
#define RB     768      // NCOLS * B_SZ
#define LSTEPS 71
#define KTOT   544      // 2*HID + CIN

// ---------------- tiling ----------------
#define BM     24       // rows per block
#define KC     32       // k per chunk
#define NCHUNK 17       // 544/32
#define NBLK   256      // grid: 8 j-tiles x 32 m-tiles
#define WS_ULL 18       // ull stride per gate-col (16 klp + 2 pad; 144B, 16B-aligned)
#define WBUF_ULL (192*WS_ULL)          // 3456 ull per W buffer
#define ABUF_F   (BM*KC)               // 768 floats per A buffer
#define SMEM_BYTES (3*ABUF_F*4 + 3*WBUF_ULL*8)   // 9216 + 82944 = 92160

// out layout: [output_all (768,71,512)] [hidden_col (32,48,256)] [hidden_row (32,24,256)]
#define OUTALL_N  (RB * LSTEPS * 2 * HID)
#define HC_N      (B_SZ * NROWS * HID)
#define HR_N      (B_SZ * NCOLS * HID)

typedef unsigned long long ull;

__device__ float g_hrow[2][RB * HID];
__device__ float g_hcol[2][RB * HID];
__device__ unsigned g_bar_cnt;
__device__ volatile unsigned g_bar_gen;

__global__ void init_kernel() { g_bar_cnt = 0; g_bar_gen = 0; }

__device__ __forceinline__ float sigmoidf_(float x) {
    return 1.0f / (1.0f + expf(-x));
}

__device__ __forceinline__ void cp16(void* dst, const void* src) {
    unsigned d = (unsigned)__cvta_generic_to_shared(dst);
    asm volatile("cp.async.ca.shared.global [%0], [%1], 16;" :: "r"(d), "l"(src));
}
__device__ __forceinline__ void cp16z(void* dst, const void* src) {
    unsigned d = (unsigned)__cvta_generic_to_shared(dst);
    asm volatile("cp.async.ca.shared.global [%0], [%1], 16, 0;" :: "r"(d), "l"(src));
}
__device__ __forceinline__ void cp_commit() {
    asm volatile("cp.async.commit_group;");
}
__device__ __forceinline__ void cp_wait1() {
    asm volatile("cp.async.wait_group 1;");
}

#define FMA2(acc, a, w) asm("fma.rn.f32x2 %0, %1, %2, %0;" : "+l"(acc) : "l"(a), "l"(w))

// Stage one 32-k chunk of A (24 rows) into A buffer c%3 via cp.async.
// A[rb][k] = { h_row(256) | rolled h_col(256) | x_s(32, masked) }.
__device__ __forceinline__ void stage_A(float* Ab, int c, int m0, int s,
    const float* __restrict__ hrow_in, const float* __restrict__ hcol_in,
    const float* __restrict__ input, int tid)
{
    if (tid >= 8 * BM) return;            // 24 rows x 8 segs of 16B
    int m = tid >> 3, seg = tid & 7;
    int rb = m0 + m;
    float* dst = Ab + (c % 3) * ABUF_F + m * KC + seg * 4;
    if (c < 8) {
        if (s == 0) cp16z(dst, input);
        else        cp16(dst, hrow_in + rb * HID + c * KC + seg * 4);
    } else if (c < 16) {
        if (s == 0) cp16z(dst, input);
        else {
            int src = rb - B_SZ; if (src < 0) src += RB;
            cp16(dst, hcol_in + src * HID + (c - 8) * KC + seg * 4);
        }
    } else {
        int r = rb >> 5, b = rb & 31, l = s - r;
        if (l >= 0 && l < NROWS)
            cp16(dst, input + (((b * NROWS) + l) * NCOLS + r) * CIN + seg * 4);
        else
            cp16z(dst, input);
    }
}

// Stage one 32-k chunk of W (192 gate-cols) into W buffer c%3 via cp.async.
// Layout: [cc][klp], cc stride 144B (18 ull). W is step-invariant.
__device__ __forceinline__ void stage_W(char* Wb_bytes, int c,
    const float* __restrict__ wsrc_base, int w_jl, int w_k4)
{
    char* db = Wb_bytes + (c % 3) * (WBUF_ULL * 8) + w_jl * 144 + w_k4 * 16;
    const float* sb = wsrc_base + c * KC;
#pragma unroll
    for (int g = 0; g < 6; ++g)
        cp16(db + g * (32 * 144), sb + g * (HID * KTOT));
}

__device__ __forceinline__ void grid_barrier(unsigned target) {
    __syncthreads();
    if (threadIdx.x == 0) {
        __threadfence();
        unsigned prev = atomicAdd(&g_bar_cnt, 1);
        if (prev == NBLK - 1) {
            g_bar_cnt = 0;
            __threadfence();
            g_bar_gen = target;
        } else {
            while (g_bar_gen < target) __nanosleep(32);
        }
        __threadfence();
    }
    __syncthreads();
}

// Persistent kernel: all 71 recurrence steps, grid barrier between steps.
// 256 blocks x 256 threads, 2 CTAs/SM. Thread tile: 6 rows x 3 gate-cols,
// f32x2 packed along K (lo=even k, hi=odd k partial sums).
__global__ __launch_bounds__(256, 2)
void witran_persistent(const float* __restrict__ input,
                       const float* __restrict__ W,
                       const float* __restrict__ Bp,
                       float* __restrict__ out)
{
    extern __shared__ char smem_raw[];
    float* Ab = (float*)smem_raw;                                 // 3 x 768 floats
    ull*   Wb = (ull*)(smem_raw + 3 * ABUF_F * 4);                // 3 x 3456 ull
    char*  Wb_bytes = (char*)Wb;
    float* Xs = (float*)(Wb + 2 * WBUF_ULL);  // gate exchange, aliases W buf 2

    const int tid     = threadIdx.x;
    const int j0      = blockIdx.x * 32;
    const int m0      = blockIdx.y * BM;
    const int slot    = tid & 63;
    const int rowslot = tid >> 6;          // 0..3, 6 rows each
    const int jl      = slot & 31;
    const int gbase   = slot >> 5;         // 0 -> gates {0,2,4}, 1 -> {1,3,5}
    const int j       = j0 + jl;

    // W staging constants (per thread: gate-col row = tid>>3, k-seg = tid&7)
    const int w_jl = tid >> 3;
    const int w_k4 = tid & 7;
    const float* wsrc_base = W + (j0 + w_jl) * KTOT + w_k4 * 4;

    float bp[3];
#pragma unroll
    for (int q = 0; q < 3; ++q) bp[q] = Bp[(gbase + 2 * q) * HID + j];

    for (int s = 0; s < LSTEPS; ++s) {
        const float* __restrict__ hrow_in  = g_hrow[s & 1];
        const float* __restrict__ hcol_in  = g_hcol[s & 1];
        float* __restrict__       hrow_out = g_hrow[(s + 1) & 1];
        float* __restrict__       hcol_out = g_hcol[(s + 1) & 1];

        // ---- prologue staging (W0/W1 already in flight for s>0) ----
        stage_A(Ab, 0, m0, s, hrow_in, hcol_in, input, tid);
        if (s == 0) stage_W(Wb_bytes, 0, wsrc_base, w_jl, w_k4);
        cp_commit();
        stage_A(Ab, 1, m0, s, hrow_in, hcol_in, input, tid);
        if (s == 0) stage_W(Wb_bytes, 1, wsrc_base, w_jl, w_k4);
        cp_commit();

        ull acc[6][3];
#pragma unroll
        for (int i = 0; i < 6; ++i)
#pragma unroll
            for (int q = 0; q < 3; ++q) acc[i][q] = 0ULL;

        for (int c = 0; c < NCHUNK; ++c) {
            cp_wait1();                     // chunk c (A and W) complete
            __syncthreads();

            if (c <= NCHUNK - 3) {          // stage chunk c+2
                stage_A(Ab, c + 2, m0, s, hrow_in, hcol_in, input, tid);
                stage_W(Wb_bytes, c + 2, wsrc_base, w_jl, w_k4);
            } else if (c == NCHUNK - 1) {   // prefetch next step's W chunk 0 (static)
                stage_W(Wb_bytes, 0, wsrc_base, w_jl, w_k4);
            }
            cp_commit();

            // ---- compute chunk c: per 2 klp: 3 LDS.128(W) + 6 LDS.128(A, bcast) + 36 FMA2 ----
            const float* abc = Ab + (c % 3) * ABUF_F + rowslot * 6 * KC;
            const ull*   wbc = Wb + (c % 3) * WBUF_ULL + slot * WS_ULL;
#pragma unroll
            for (int klp2 = 0; klp2 < 16; klp2 += 2) {
                ulonglong2 wv0 = *(const ulonglong2*)(wbc + klp2);
                ulonglong2 wv1 = *(const ulonglong2*)(wbc + 64 * WS_ULL + klp2);
                ulonglong2 wv2 = *(const ulonglong2*)(wbc + 128 * WS_ULL + klp2);
#pragma unroll
                for (int i = 0; i < 6; ++i) {
                    ulonglong2 av = *(const ulonglong2*)(abc + i * KC + klp2 * 2);
                    FMA2(acc[i][0], av.x, wv0.x);
                    FMA2(acc[i][1], av.x, wv1.x);
                    FMA2(acc[i][2], av.x, wv2.x);
                    FMA2(acc[i][0], av.y, wv0.y);
                    FMA2(acc[i][1], av.y, wv1.y);
                    FMA2(acc[i][2], av.y, wv2.y);
                }
            }
        }

        // ---- epilogue: reduce halves, apply mask+bias, exchange, PSGMU update ----
        float gv[6][3];
#pragma unroll
        for (int i = 0; i < 6; ++i) {
            int rb = m0 + rowslot * 6 + i;
            bool mask = (s < NCOLS) && ((rb >> 5) <= s);
#pragma unroll
            for (int q = 0; q < 3; ++q) {
                ull v = acc[i][q];
                float g = __uint_as_float((unsigned)(v & 0xffffffffULL)) +
                          __uint_as_float((unsigned)(v >> 32));
                gv[i][q] = mask ? (g + bp[q]) : g;
            }
        }

        if (gbase == 1) {   // owns o_row(1), o_col(3), i_col(5)
#pragma unroll
            for (int i = 0; i < 6; ++i) {
                int row = rowslot * 6 + i;
                Xs[row * 96 + jl * 3 + 0] = sigmoidf_(gv[i][0]);
                Xs[row * 96 + jl * 3 + 1] = sigmoidf_(gv[i][1]);
                Xs[row * 96 + jl * 3 + 2] = tanhf(gv[i][2]);
            }
        }
        __syncthreads();

        // prefetch next step's W chunk 1 (static) — buf 1 free after the sync
        stage_W(Wb_bytes, 1, wsrc_base, w_jl, w_k4);
        cp_commit();

        if (gbase == 0) {   // owns u_row(0), u_col(2), i_row(4)
#pragma unroll
            for (int i = 0; i < 6; ++i) {
                int row = rowslot * 6 + i;
                int rb = m0 + row;
                float u_row = sigmoidf_(gv[i][0]);
                float u_col = sigmoidf_(gv[i][1]);
                float i_row = tanhf(gv[i][2]);
                float o_row = Xs[row * 96 + jl * 3 + 0];
                float o_col = Xs[row * 96 + jl * 3 + 1];
                float i_col = Xs[row * 96 + jl * 3 + 2];

                int src = rb - B_SZ; if (src < 0) src += RB;
                float hro = (s == 0) ? 0.0f : hrow_in[rb * HID + j];
                float hco = (s == 0) ? 0.0f : hcol_in[src * HID + j];

                float hr = tanhf((1.0f - u_row) * hro + u_row * i_row) * o_row;
                float hc = tanhf((1.0f - u_col) * hco + u_col * i_col) * o_col;

                hrow_out[rb * HID + j] = hr;
                hcol_out[rb * HID + j] = hc;

                float* orow = out + ((size_t)rb * LSTEPS + s) * (2 * HID);
                orow[j]       = hr;
                orow[HID + j] = hc;
            }
        }

        grid_barrier((unsigned)(s + 1));
    }
}

// Gather hidden_col_all / hidden_row_all from output_all (disjoint regions of d_out).
__global__ void gather_kernel(float* __restrict__ out) {
    int idx = blockIdx.x * blockDim.x + threadIdx.x;
    if (idx < HC_N) {
        int b = idx / (NROWS * HID);
        int t = (idx / HID) % NROWS;
        int j = idx % HID;
        int rb = (NCOLS - 1) * B_SZ + b;
        int ss = (NCOLS - 1) + t;
        out[OUTALL_N + idx] = out[((size_t)rb * LSTEPS + ss) * (2 * HID) + HID + j];
    } else if (idx < HC_N + HR_N) {
        int k = idx - HC_N;
        int b = k / (NCOLS * HID);
        int i = (k / HID) % NCOLS;
        int j = k % HID;
        int rb = i * B_SZ + b;
        int ss = (NROWS - 1) + i;
        out[OUTALL_N + HC_N + k] = out[((size_t)rb * LSTEPS + ss) * (2 * HID) + j];
    }
}

extern "C" void kernel_launch(void* const* d_in, const int* in_sizes, int n_in,
                              void* d_out, int out_size) {
    (void)in_sizes; (void)n_in; (void)out_size;
    const float* input = (const float*)d_in[0];   // (32,48,24,32)
    const float* W     = (const float*)d_in[1];   // (1536,544)
    const float* Bp    = (const float*)d_in[2];   // (1536,)
    float* out = (float*)d_out;

    cudaFuncSetAttribute(witran_persistent,
                         cudaFuncAttributeMaxDynamicSharedMemorySize, SMEM_BYTES);

    init_kernel<<<1, 1>>>();

    dim3 grid(HID / 32, RB / BM);   // (8, 32) = 256 blocks, 2 CTAs/SM, all resident
    witran_persistent<<<grid, 256, SMEM_BYTES>>>(input, W, Bp, out);

    gather_kernel<<<(HC_N + HR_N + 255) / 256, 256>>>(out);
}